// round 9
// baseline (speedup 1.0000x reference)
#include <cuda_runtime.h>
#include <cstdint>

#define NN 50000
#define NE 1200000
#define INC 128
#define HC 64
#define OC 64
#define SB 196                     // scan blocks (196*256 = 50176 >= NN)
#define GB 1563                    // gemm blocks ((NN+31)/32)
#define HB ((NE + 127) / 128)      // hist blocks at 128 threads
#define SCTB ((NE + 1023) / 1024)  // scatter blocks (4 edges/thread, 256 thr)

#define NEG_INF __int_as_float(0xff800000)

typedef unsigned long long ull;

// ---------------- scratch ----------------
__device__ __align__(16) float g_xl[(size_t)NN * HC];
__device__ __align__(16) float g_xr[(size_t)NN * HC];
__device__ __align__(16) float g_Wt[INC * 128];
__device__ __align__(16) float g_Wlt[HC * OC];
__device__ int   g_cnt[SB * 256];      // degree counts; zeroed by scan for next replay
__device__ int   g_off[NN + 1];
__device__ int   g_srcs[NE];
__device__ __align__(16) ull g_dr[NE]; // packed (dst<<16|src)<<32 | rank
__device__ int   g_flag[SB];           // lookback: 0=invalid 1=agg 2=inclusive
__device__ int   g_agg[SB];
__device__ int   g_incl[SB];
__device__ int   g_scan_done;          // count of finished scan blocks
__device__ int   g_probe;              // 1 => int32 storage, 0 => int64

// ---------------- helpers ----------------
__device__ __forceinline__ ull pack2(float lo, float hi) {
    ull r; asm("mov.b64 %0, {%1, %2};" : "=l"(r) : "f"(lo), "f"(hi)); return r;
}
__device__ __forceinline__ void unpack2(ull v, float& lo, float& hi) {
    asm("mov.b64 {%0, %1}, %2;" : "=f"(lo), "=f"(hi) : "l"(v));
}
__device__ __forceinline__ void ffma2(ull& d, ull a, ull b) {
    asm("fma.rn.f32x2 %0, %1, %2, %0;" : "+l"(d) : "l"(a), "l"(b));
}
__device__ __forceinline__ int load_idx(const void* ei, int pos, int is64) {
    int v = is64 ? (int)((const long long*)ei)[pos] : ((const int*)ei)[pos];
    return (v < 0) ? 0 : (v >= NN ? NN - 1 : v);
}

// ---------------- K0: weight transpose + dtype probe + control resets ----------------
__global__ void k_pre(const float* __restrict__ Wl, const float* __restrict__ Wr,
                      const float* __restrict__ Wlin, const int* __restrict__ ei32) {
    int t0 = blockIdx.x * blockDim.x + threadIdx.x;
    if (t0 < 32) {
        int v = 0;
#pragma unroll 8
        for (int it = 0; it < 32; it++) v |= ei32[2 * (t0 + 32 * it) + 1];
#pragma unroll
        for (int o = 16; o; o >>= 1) v |= __shfl_xor_sync(0xffffffffu, v, o);
        if (t0 == 0) { g_probe = (v != 0) ? 1 : 0; g_scan_done = 0; }
    }
    if (t0 < SB) g_flag[t0] = 0;
    if (t0 < INC * 128) {
        int k = t0 >> 7, ch = t0 & 127;
        g_Wt[t0] = (ch < HC) ? Wl[ch * INC + k] : Wr[(ch - HC) * INC + k];
    }
    if (t0 < HC * OC) {
        int k = t0 >> 6, o = t0 & 63;
        g_Wlt[t0] = Wlin[o * HC + k];
    }
}

// ---------------- K1: MERGED projection GEMM + histogram/pack (grid-partitioned) ----------------
__global__ void __launch_bounds__(128) k_gh(const float* __restrict__ x,
                                            const void* __restrict__ ei) {
    __shared__ __align__(16) float xs2[32 * INC];
    int tid = threadIdx.x;

    if (blockIdx.x >= GB) {
        int is64 = (g_probe == 0);
        int e = (blockIdx.x - GB) * 128 + tid;
        if (e < NE) {
            int d = load_idx(ei, NE + e, is64);
            int s = load_idx(ei, e, is64);
            int r = atomicAdd(&g_cnt[d], 1);
            g_dr[e] = ((ull)(((unsigned)d << 16) | (unsigned)s) << 32) | (unsigned)r;
        }
        return;
    }

    int row0 = blockIdx.x * 32;
    int nrows = NN - row0; if (nrows > 32) nrows = 32;

    for (int i = tid; i < 32 * (INC / 4); i += 128) {
        int r = i >> 5;
        int k4 = (i & 31) << 2;
        if (r < nrows) {
            float4 v = *(const float4*)(x + (size_t)(row0 + r) * INC + k4);
            float* b = xs2 + (r >> 1) * (2 * INC) + (r & 1);
            b[2 * k4 + 0] = v.x; b[2 * k4 + 2] = v.y;
            b[2 * k4 + 4] = v.z; b[2 * k4 + 6] = v.w;
        }
    }
    __syncthreads();

    int warp = tid >> 5, lane = tid & 31;
    int c = lane << 2;
    ull acc[4][4];
#pragma unroll
    for (int q = 0; q < 4; q++)
#pragma unroll
        for (int j = 0; j < 4; j++) acc[q][j] = 0ull;

    const float* xb = xs2 + (warp * 4) * (2 * INC);
#pragma unroll 8
    for (int k = 0; k < INC; k++) {
        float4 w = *(const float4*)(g_Wt + (k << 7) + c);
        ull w0 = pack2(w.x, w.x), w1 = pack2(w.y, w.y);
        ull w2 = pack2(w.z, w.z), w3 = pack2(w.w, w.w);
#pragma unroll
        for (int q = 0; q < 4; q++) {
            ull xp = *(const ull*)(xb + q * (2 * INC) + 2 * k);
            ffma2(acc[q][0], xp, w0);
            ffma2(acc[q][1], xp, w1);
            ffma2(acc[q][2], xp, w2);
            ffma2(acc[q][3], xp, w3);
        }
    }

    float* base = (c < HC) ? (g_xl + c) : (g_xr + (c - HC));
#pragma unroll
    for (int q = 0; q < 4; q++) {
        int re = row0 + warp * 8 + q * 2;
        if (re >= NN) break;
        float lo0, hi0, lo1, hi1, lo2, hi2, lo3, hi3;
        unpack2(acc[q][0], lo0, hi0); unpack2(acc[q][1], lo1, hi1);
        unpack2(acc[q][2], lo2, hi2); unpack2(acc[q][3], lo3, hi3);
        *(float4*)(base + (size_t)re * HC) = make_float4(lo0, lo1, lo2, lo3);
        if (re + 1 < NN)
            *(float4*)(base + (size_t)(re + 1) * HC) = make_float4(hi0, hi1, hi2, hi3);
    }
}

// ---------------- K2: MERGED decoupled-lookback scan + scatter (grid-partitioned) ----------------
// Blocks [0,SB) scan (all chip-resident in wave 1 -> lookback deadlock-free) and bump
// g_scan_done; blocks [SB, SB+SCTB) wait for the counter then scatter 4 edges/thread.
__global__ void __launch_bounds__(256) k_ss() {
    int tid = threadIdx.x;
    int b = blockIdx.x;

    if (b < SB) {
        __shared__ int wsum[8];
        __shared__ int s_base;
        int i = b * 256 + tid;
        int v = g_cnt[i];
        g_cnt[i] = 0;                       // reset for next replay
        int lane = tid & 31, wid = tid >> 5;
        int xv = v;
#pragma unroll
        for (int o = 1; o < 32; o <<= 1) {
            int y = __shfl_up_sync(0xffffffffu, xv, o);
            if (lane >= o) xv += y;
        }
        if (lane == 31) wsum[wid] = xv;
        __syncthreads();
        if (tid < 8) {
            int w = wsum[tid];
#pragma unroll
            for (int o = 1; o < 8; o <<= 1) {
                int y = __shfl_up_sync(0x000000ffu, w, o);
                if (tid >= o) w += y;
            }
            wsum[tid] = w;
        }
        __syncthreads();
        int excl = xv - v + ((wid > 0) ? wsum[wid - 1] : 0);
        int T = wsum[7];

        if (b == 0) {
            if (tid == 0) {
                g_incl[0] = T;
                __threadfence();
                atomicExch(&g_flag[0], 2);
                s_base = 0;
            }
        } else if (tid < 32) {
            if (tid == 0) {
                g_agg[b] = T;
                __threadfence();
                atomicExch(&g_flag[b], 1);
            }
            __syncwarp();
            int sum = 0;
            int p = b - 1;
            int lane2 = tid;
            for (;;) {
                int idx = p - lane2;
                int f = 0;
                if (idx >= 0) {
                    do { f = atomicAdd(&g_flag[idx], 0); } while (f == 0);
                }
                unsigned m2 = __ballot_sync(0xffffffffu, (idx >= 0) && (f == 2));
                int kcut = m2 ? (__ffs(m2) - 1) : 32;
                __threadfence();
                int contrib = 0;
                if (idx >= 0 && lane2 <= kcut)
                    contrib = (lane2 == kcut) ? atomicAdd(&g_incl[idx], 0)
                                              : atomicAdd(&g_agg[idx], 0);
#pragma unroll
                for (int o = 16; o; o >>= 1) contrib += __shfl_xor_sync(0xffffffffu, contrib, o);
                sum += contrib;
                if (m2) break;
                p -= 32;
            }
            if (tid == 0) {
                g_incl[b] = sum + T;
                __threadfence();
                atomicExch(&g_flag[b], 2);
                s_base = sum;
            }
        }
        __syncthreads();
        if (i < NN) g_off[i] = excl + s_base;
        if (b == 0 && tid == 0) g_off[NN] = NE;
        __threadfence();
        __syncthreads();
        if (tid == 0) atomicAdd(&g_scan_done, 1);
        return;
    }

    // ---- scatter part: wait for scan completion ----
    if (tid == 0) {
        while (atomicAdd(&g_scan_done, 0) < SB) __nanosleep(64);
    }
    __syncthreads();
    __threadfence();

    int e0 = (b - SB) * 1024 + tid;
#pragma unroll
    for (int k = 0; k < 4; k++) {
        int e = e0 + k * 256;
        if (e < NE) {
            ull dr = g_dr[e];
            unsigned hi = (unsigned)(dr >> 32);
            int d = hi >> 16;
            int s = hi & 0xFFFF;
            int r = (int)(unsigned)dr;
            g_srcs[g_off[d] + r] = s;
        }
    }
}

// ---------------- K3: no-max softmax aggregation (quarter-parallel) + fused out GEMM ----------------
// 1024-thread blocks: sW staged once per 32 nodes (4x less W_lin L2 traffic than 256-thr).
__global__ void __launch_bounds__(1024) k_aggr(const float* __restrict__ att,
                                               const float* __restrict__ bias,
                                               const float* __restrict__ blin,
                                               float* __restrict__ out) {
    __shared__ __align__(16) float sW[HC * OC];   // 16 KB
    __shared__ __align__(16) float sh[32][HC];    // 8 KB
    __shared__ int ssrc[32][64];                  // 8 KB
    int tid = threadIdx.x;
    if (tid < 1024) *(float4*)&sW[tid * 4] = *(const float4*)&g_Wlt[tid * 4];
    __syncthreads();

    int warp = tid >> 5, lane = tid & 31;
    int i = blockIdx.x * 32 + warp;
    if (i >= NN) return;

    int quarter = lane >> 3, l8 = lane & 7;
    int ch = l8 * 8;
    float4 a0  = *(const float4*)(att + ch);
    float4 a1  = *(const float4*)(att + ch + 4);
    float4 xr0 = *(const float4*)(g_xr + (size_t)i * HC + ch);
    float4 xr1 = *(const float4*)(g_xr + (size_t)i * HC + ch + 4);

    float d = 0.0f;
    float acc[8];
#pragma unroll
    for (int k = 0; k < 8; k++) acc[k] = 0.0f;

    int off = g_off[i];
    int tcount = g_off[i + 1] - off + 1;      // +1: self loop at t==0

    for (int base = 0; base < tcount; base += 64) {
        int n = tcount - base; if (n > 64) n = 64;
        for (int t = lane; t < n; t += 32) {
            int g = base + t;
            ssrc[warp][t] = (g == 0) ? i : g_srcs[off + g - 1];
        }
        __syncwarp();

#pragma unroll 4
        for (int t0 = 0; t0 < n; t0 += 4) {
            int my = t0 + quarter;
            bool valid = (my < n);
            int j = valid ? ssrc[warp][my] : i;
            const float* vp = g_xl + (size_t)j * HC + ch;
            float4 v0 = *(const float4*)vp;
            float4 v1 = *(const float4*)(vp + 4);
            float u, s;
            u = v0.x + xr0.x; s  = fmaxf(u, 0.2f * u) * a0.x;
            u = v0.y + xr0.y; s += fmaxf(u, 0.2f * u) * a0.y;
            u = v0.z + xr0.z; s += fmaxf(u, 0.2f * u) * a0.z;
            u = v0.w + xr0.w; s += fmaxf(u, 0.2f * u) * a0.w;
            u = v1.x + xr1.x; s += fmaxf(u, 0.2f * u) * a1.x;
            u = v1.y + xr1.y; s += fmaxf(u, 0.2f * u) * a1.y;
            u = v1.z + xr1.z; s += fmaxf(u, 0.2f * u) * a1.z;
            u = v1.w + xr1.w; s += fmaxf(u, 0.2f * u) * a1.w;
            float q = valid ? s : NEG_INF;
            q += __shfl_xor_sync(0xffffffffu, q, 1);
            q += __shfl_xor_sync(0xffffffffu, q, 2);
            q += __shfl_xor_sync(0xffffffffu, q, 4);
            float pe = __expf(q);
            d += pe;
            acc[0] += pe * v0.x; acc[1] += pe * v0.y;
            acc[2] += pe * v0.z; acc[3] += pe * v0.w;
            acc[4] += pe * v1.x; acc[5] += pe * v1.y;
            acc[6] += pe * v1.z; acc[7] += pe * v1.w;
        }
        __syncwarp();
    }

    d += __shfl_xor_sync(0xffffffffu, d, 8);
    d += __shfl_xor_sync(0xffffffffu, d, 16);
#pragma unroll
    for (int k = 0; k < 8; k++) acc[k] += __shfl_xor_sync(0xffffffffu, acc[k], 8);
#pragma unroll
    for (int k = 0; k < 8; k++) acc[k] += __shfl_xor_sync(0xffffffffu, acc[k], 16);

    float inv = 1.0f / (d + 1e-16f);
    float4 b0 = *(const float4*)(bias + ch);
    float4 b1 = *(const float4*)(bias + ch + 4);
    float h[8];
    h[0] = acc[0] * inv + b0.x; h[1] = acc[1] * inv + b0.y;
    h[2] = acc[2] * inv + b0.z; h[3] = acc[3] * inv + b0.w;
    h[4] = acc[4] * inv + b1.x; h[5] = acc[5] * inv + b1.y;
    h[6] = acc[6] * inv + b1.z; h[7] = acc[7] * inv + b1.w;
#pragma unroll
    for (int k = 0; k < 8; k++) h[k] = (h[k] > 0.0f) ? h[k] : expm1f(h[k]);

    if (quarter == 0) {
        *(float4*)&sh[warp][ch]     = make_float4(h[0], h[1], h[2], h[3]);
        *(float4*)&sh[warp][ch + 4] = make_float4(h[4], h[5], h[6], h[7]);
    }
    __syncwarp();

    int c = lane << 1;
    ull acc2 = 0ull;
    const float* hr = sh[warp];
#pragma unroll 4
    for (int k4 = 0; k4 < 16; k4++) {
        float4 hq = *(const float4*)&hr[k4 * 4];
        ffma2(acc2, pack2(hq.x, hq.x), *(const ull*)&sW[(k4 * 4 + 0) * OC + c]);
        ffma2(acc2, pack2(hq.y, hq.y), *(const ull*)&sW[(k4 * 4 + 1) * OC + c]);
        ffma2(acc2, pack2(hq.z, hq.z), *(const ull*)&sW[(k4 * 4 + 2) * OC + c]);
        ffma2(acc2, pack2(hq.w, hq.w), *(const ull*)&sW[(k4 * 4 + 3) * OC + c]);
    }
    float o0, o1; unpack2(acc2, o0, o1);
    float2 bl = *(const float2*)(blin + c);
    *(float2*)(out + (size_t)i * OC + c) = make_float2(o0 + bl.x, o1 + bl.y);
}

// ---------------- launch ----------------
extern "C" void kernel_launch(void* const* d_in, const int* in_sizes, int n_in,
                              void* d_out, int out_size) {
    const float* x     = (const float*)d_in[0];
    const void*  ei    = d_in[1];
    const float* Wl    = (const float*)d_in[3];
    const float* Wr    = (const float*)d_in[4];
    const float* att   = (const float*)d_in[5];
    const float* bconv = (const float*)d_in[6];
    const float* Wlin  = (const float*)d_in[7];
    const float* blin  = (const float*)d_in[8];
    float* out = (float*)d_out;

    k_pre<<<196, 256>>>(Wl, Wr, Wlin, (const int*)ei);
    k_gh<<<GB + HB, 128>>>(x, ei);
    k_ss<<<SB + SCTB, 256>>>();
    k_aggr<<<(NN + 31) / 32, 1024>>>(att, bconv, blin, out);
}

// round 11
// speedup vs baseline: 1.0370x; 1.0370x over previous
#include <cuda_runtime.h>
#include <cstdint>

#define NN 50000
#define NE 1200000
#define INC 128
#define HC 64
#define OC 64
#define SB 196                     // scan blocks (196*256 = 50176 >= NN)
#define GB 1563                    // gemm blocks ((NN+31)/32)
#define HB ((NE + 127) / 128)      // hist blocks at 128 threads
#define SCTB ((NE + 1023) / 1024)  // scatter blocks (4 edges/thread, 256 thr)

#define NEG_INF __int_as_float(0xff800000)

typedef unsigned long long ull;

// ---------------- scratch ----------------
__device__ __align__(16) float g_xl[(size_t)NN * HC];
__device__ __align__(16) float g_xr[(size_t)NN * HC];
__device__ __align__(16) float g_Wt[INC * 128];
__device__ __align__(16) float g_Wlt[HC * OC];
__device__ int   g_cnt[SB * 256];      // degree counts; zeroed by scan for next replay
__device__ int   g_off[NN + 1];
__device__ int   g_srcs[NE];
__device__ __align__(16) ull g_dr[NE]; // packed (dst<<16|src)<<32 | rank
__device__ int   g_flag[SB];           // lookback: 0=invalid 1=agg 2=inclusive
__device__ int   g_agg[SB];
__device__ int   g_incl[SB];
__device__ int   g_scan_done;
__device__ int   g_probe;              // 1 => int32 storage, 0 => int64

// ---------------- helpers ----------------
__device__ __forceinline__ ull pack2(float lo, float hi) {
    ull r; asm("mov.b64 %0, {%1, %2};" : "=l"(r) : "f"(lo), "f"(hi)); return r;
}
__device__ __forceinline__ void unpack2(ull v, float& lo, float& hi) {
    asm("mov.b64 {%0, %1}, %2;" : "=f"(lo), "=f"(hi) : "l"(v));
}
__device__ __forceinline__ void ffma2(ull& d, ull a, ull b) {
    asm("fma.rn.f32x2 %0, %1, %2, %0;" : "+l"(d) : "l"(a), "l"(b));
}
__device__ __forceinline__ int load_idx(const void* ei, int pos, int is64) {
    int v = is64 ? (int)((const long long*)ei)[pos] : ((const int*)ei)[pos];
    return (v < 0) ? 0 : (v >= NN ? NN - 1 : v);
}

// ---------------- K0: weight transpose + dtype probe + control resets ----------------
__global__ void k_pre(const float* __restrict__ Wl, const float* __restrict__ Wr,
                      const float* __restrict__ Wlin, const int* __restrict__ ei32) {
    int t0 = blockIdx.x * blockDim.x + threadIdx.x;
    if (t0 < 32) {
        int v = 0;
#pragma unroll 8
        for (int it = 0; it < 32; it++) v |= ei32[2 * (t0 + 32 * it) + 1];
#pragma unroll
        for (int o = 16; o; o >>= 1) v |= __shfl_xor_sync(0xffffffffu, v, o);
        if (t0 == 0) { g_probe = (v != 0) ? 1 : 0; g_scan_done = 0; }
    }
    if (t0 < SB) g_flag[t0] = 0;
    if (t0 < INC * 128) {
        int k = t0 >> 7, ch = t0 & 127;
        g_Wt[t0] = (ch < HC) ? Wl[ch * INC + k] : Wr[(ch - HC) * INC + k];
    }
    if (t0 < HC * OC) {
        int k = t0 >> 6, o = t0 & 63;
        g_Wlt[t0] = Wlin[o * HC + k];
    }
}

// ---------------- K1: MERGED projection GEMM + histogram/pack ----------------
__global__ void __launch_bounds__(128) k_gh(const float* __restrict__ x,
                                            const void* __restrict__ ei) {
    __shared__ __align__(16) float xs2[32 * INC];
    int tid = threadIdx.x;

    if (blockIdx.x >= GB) {
        int is64 = (g_probe == 0);
        int e = (blockIdx.x - GB) * 128 + tid;
        if (e < NE) {
            int d = load_idx(ei, NE + e, is64);
            int s = load_idx(ei, e, is64);
            int r = atomicAdd(&g_cnt[d], 1);
            g_dr[e] = ((ull)(((unsigned)d << 16) | (unsigned)s) << 32) | (unsigned)r;
        }
        return;
    }

    int row0 = blockIdx.x * 32;
    int nrows = NN - row0; if (nrows > 32) nrows = 32;

    for (int i = tid; i < 32 * (INC / 4); i += 128) {
        int r = i >> 5;
        int k4 = (i & 31) << 2;
        if (r < nrows) {
            float4 v = *(const float4*)(x + (size_t)(row0 + r) * INC + k4);
            float* b = xs2 + (r >> 1) * (2 * INC) + (r & 1);
            b[2 * k4 + 0] = v.x; b[2 * k4 + 2] = v.y;
            b[2 * k4 + 4] = v.z; b[2 * k4 + 6] = v.w;
        }
    }
    __syncthreads();

    int warp = tid >> 5, lane = tid & 31;
    int c = lane << 2;
    ull acc[4][4];
#pragma unroll
    for (int q = 0; q < 4; q++)
#pragma unroll
        for (int j = 0; j < 4; j++) acc[q][j] = 0ull;

    const float* xb = xs2 + (warp * 4) * (2 * INC);
#pragma unroll 8
    for (int k = 0; k < INC; k++) {
        float4 w = *(const float4*)(g_Wt + (k << 7) + c);
        ull w0 = pack2(w.x, w.x), w1 = pack2(w.y, w.y);
        ull w2 = pack2(w.z, w.z), w3 = pack2(w.w, w.w);
#pragma unroll
        for (int q = 0; q < 4; q++) {
            ull xp = *(const ull*)(xb + q * (2 * INC) + 2 * k);
            ffma2(acc[q][0], xp, w0);
            ffma2(acc[q][1], xp, w1);
            ffma2(acc[q][2], xp, w2);
            ffma2(acc[q][3], xp, w3);
        }
    }

    float* base = (c < HC) ? (g_xl + c) : (g_xr + (c - HC));
#pragma unroll
    for (int q = 0; q < 4; q++) {
        int re = row0 + warp * 8 + q * 2;
        if (re >= NN) break;
        float lo0, hi0, lo1, hi1, lo2, hi2, lo3, hi3;
        unpack2(acc[q][0], lo0, hi0); unpack2(acc[q][1], lo1, hi1);
        unpack2(acc[q][2], lo2, hi2); unpack2(acc[q][3], lo3, hi3);
        *(float4*)(base + (size_t)re * HC) = make_float4(lo0, lo1, lo2, lo3);
        if (re + 1 < NN)
            *(float4*)(base + (size_t)(re + 1) * HC) = make_float4(hi0, hi1, hi2, hi3);
    }
}

// ---------------- K2: MERGED decoupled-lookback scan + scatter ----------------
__global__ void __launch_bounds__(256) k_ss() {
    int tid = threadIdx.x;
    int b = blockIdx.x;

    if (b < SB) {
        __shared__ int wsum[8];
        __shared__ int s_base;
        int i = b * 256 + tid;
        int v = g_cnt[i];
        g_cnt[i] = 0;
        int lane = tid & 31, wid = tid >> 5;
        int xv = v;
#pragma unroll
        for (int o = 1; o < 32; o <<= 1) {
            int y = __shfl_up_sync(0xffffffffu, xv, o);
            if (lane >= o) xv += y;
        }
        if (lane == 31) wsum[wid] = xv;
        __syncthreads();
        if (tid < 8) {
            int w = wsum[tid];
#pragma unroll
            for (int o = 1; o < 8; o <<= 1) {
                int y = __shfl_up_sync(0x000000ffu, w, o);
                if (tid >= o) w += y;
            }
            wsum[tid] = w;
        }
        __syncthreads();
        int excl = xv - v + ((wid > 0) ? wsum[wid - 1] : 0);
        int T = wsum[7];

        if (b == 0) {
            if (tid == 0) {
                g_incl[0] = T;
                __threadfence();
                atomicExch(&g_flag[0], 2);
                s_base = 0;
            }
        } else if (tid < 32) {
            if (tid == 0) {
                g_agg[b] = T;
                __threadfence();
                atomicExch(&g_flag[b], 1);
            }
            __syncwarp();
            int sum = 0;
            int p = b - 1;
            for (;;) {
                int idx = p - tid;
                int f = 0;
                if (idx >= 0) {
                    do { f = atomicAdd(&g_flag[idx], 0); } while (f == 0);
                }
                unsigned m2 = __ballot_sync(0xffffffffu, (idx >= 0) && (f == 2));
                int kcut = m2 ? (__ffs(m2) - 1) : 32;
                __threadfence();
                int contrib = 0;
                if (idx >= 0 && tid <= kcut)
                    contrib = (tid == kcut) ? atomicAdd(&g_incl[idx], 0)
                                            : atomicAdd(&g_agg[idx], 0);
#pragma unroll
                for (int o = 16; o; o >>= 1) contrib += __shfl_xor_sync(0xffffffffu, contrib, o);
                sum += contrib;
                if (m2) break;
                p -= 32;
            }
            if (tid == 0) {
                g_incl[b] = sum + T;
                __threadfence();
                atomicExch(&g_flag[b], 2);
                s_base = sum;
            }
        }
        __syncthreads();
        if (i < NN) g_off[i] = excl + s_base;
        if (b == 0 && tid == 0) g_off[NN] = NE;
        __threadfence();
        __syncthreads();
        if (tid == 0) atomicAdd(&g_scan_done, 1);
        return;
    }

    if (tid == 0) {
        while (atomicAdd(&g_scan_done, 0) < SB) __nanosleep(64);
    }
    __syncthreads();
    __threadfence();

    int e0 = (b - SB) * 1024 + tid;
#pragma unroll
    for (int k = 0; k < 4; k++) {
        int e = e0 + k * 256;
        if (e < NE) {
            ull dr = g_dr[e];
            unsigned hi = (unsigned)(dr >> 32);
            int d = hi >> 16;
            int s = hi & 0xFFFF;
            int r = (int)(unsigned)dr;
            g_srcs[g_off[d] + r] = s;
        }
    }
}

// ---------------- K3: aggregation, contiguous-line gathers + abs-trick logits ----------------
// Warp per node; 8-lane quarters each own one edge/iter. Lane owns channels
// [l8*4, l8*4+4) and [32+l8*4, 32+l8*4+4) -> each quarter's v0/v1 LDG.128 covers
// exactly one 128B line. leaky_relu(u) = 0.6u + 0.4|u| (exact) with pre-scaled att.
// Self-loop seed runs in ALL quarters -> scaled by 0.25 so the quarter-merge tree
// (pe/4+pe/4=pe/2, pe/2+pe/2=pe: exact) counts it exactly once.
__global__ void __launch_bounds__(512) k_aggr(const float* __restrict__ att,
                                              const float* __restrict__ bias,
                                              const float* __restrict__ blin,
                                              float* __restrict__ out) {
    __shared__ __align__(16) float sW[HC * OC];   // 16 KB
    __shared__ __align__(16) float sh[16][HC];    // 4 KB
    int tid = threadIdx.x;
    for (int idx = tid; idx < HC * OC / 4; idx += 512)
        *(float4*)&sW[idx * 4] = *(const float4*)&g_Wlt[idx * 4];
    __syncthreads();

    int warp = tid >> 5, lane = tid & 31;
    int i = blockIdx.x * 16 + warp;
    if (i >= NN) return;

    int quarter = lane >> 3, l8 = lane & 7;
    int c0 = l8 * 4, c1 = 32 + l8 * 4;            // contiguous per-quarter lines

    float4 at0 = *(const float4*)(att + c0);
    float4 at1 = *(const float4*)(att + c1);
    float4 a6_0 = make_float4(0.6f * at0.x, 0.6f * at0.y, 0.6f * at0.z, 0.6f * at0.w);
    float4 a6_1 = make_float4(0.6f * at1.x, 0.6f * at1.y, 0.6f * at1.z, 0.6f * at1.w);
    float4 a4_0 = make_float4(0.4f * at0.x, 0.4f * at0.y, 0.4f * at0.z, 0.4f * at0.w);
    float4 a4_1 = make_float4(0.4f * at1.x, 0.4f * at1.y, 0.4f * at1.z, 0.4f * at1.w);

    const float* xri = g_xr + ((unsigned)i << 6);
    float4 xr0 = *(const float4*)(xri + c0);
    float4 xr1 = *(const float4*)(xri + c1);

    // ---- self loop: all quarters compute it; 0.25 scale => merge counts it once ----
    const float* xli = g_xl + ((unsigned)i << 6);
    float4 v0 = *(const float4*)(xli + c0);
    float4 v1 = *(const float4*)(xli + c1);
    float u, s = 0.0f;
    u = v0.x + xr0.x; s = fmaf(u, a6_0.x, s); s = fmaf(fabsf(u), a4_0.x, s);
    u = v0.y + xr0.y; s = fmaf(u, a6_0.y, s); s = fmaf(fabsf(u), a4_0.y, s);
    u = v0.z + xr0.z; s = fmaf(u, a6_0.z, s); s = fmaf(fabsf(u), a4_0.z, s);
    u = v0.w + xr0.w; s = fmaf(u, a6_0.w, s); s = fmaf(fabsf(u), a4_0.w, s);
    u = v1.x + xr1.x; s = fmaf(u, a6_1.x, s); s = fmaf(fabsf(u), a4_1.x, s);
    u = v1.y + xr1.y; s = fmaf(u, a6_1.y, s); s = fmaf(fabsf(u), a4_1.y, s);
    u = v1.z + xr1.z; s = fmaf(u, a6_1.z, s); s = fmaf(fabsf(u), a4_1.z, s);
    u = v1.w + xr1.w; s = fmaf(u, a6_1.w, s); s = fmaf(fabsf(u), a4_1.w, s);
    s += __shfl_xor_sync(0xffffffffu, s, 1);
    s += __shfl_xor_sync(0xffffffffu, s, 2);
    s += __shfl_xor_sync(0xffffffffu, s, 4);
    float pe = 0.25f * __expf(s);
    float d = pe;
    float acc[8];
    acc[0] = pe * v0.x; acc[1] = pe * v0.y; acc[2] = pe * v0.z; acc[3] = pe * v0.w;
    acc[4] = pe * v1.x; acc[5] = pe * v1.y; acc[6] = pe * v1.z; acc[7] = pe * v1.w;

    // ---- edges: 4 in flight (one per quarter), direct LDG, no staging ----
    int off = g_off[i], end = g_off[i + 1];
    for (int e = off; e < end; e += 4) {
        int my = e + quarter;
        bool valid = (my < end);
        int j = valid ? g_srcs[my] : i;
        const float* vp = g_xl + ((unsigned)j << 6);
        v0 = *(const float4*)(vp + c0);
        v1 = *(const float4*)(vp + c1);
        s = 0.0f;
        u = v0.x + xr0.x; s = fmaf(u, a6_0.x, s); s = fmaf(fabsf(u), a4_0.x, s);
        u = v0.y + xr0.y; s = fmaf(u, a6_0.y, s); s = fmaf(fabsf(u), a4_0.y, s);
        u = v0.z + xr0.z; s = fmaf(u, a6_0.z, s); s = fmaf(fabsf(u), a4_0.z, s);
        u = v0.w + xr0.w; s = fmaf(u, a6_0.w, s); s = fmaf(fabsf(u), a4_0.w, s);
        u = v1.x + xr1.x; s = fmaf(u, a6_1.x, s); s = fmaf(fabsf(u), a4_1.x, s);
        u = v1.y + xr1.y; s = fmaf(u, a6_1.y, s); s = fmaf(fabsf(u), a4_1.y, s);
        u = v1.z + xr1.z; s = fmaf(u, a6_1.z, s); s = fmaf(fabsf(u), a4_1.z, s);
        u = v1.w + xr1.w; s = fmaf(u, a6_1.w, s); s = fmaf(fabsf(u), a4_1.w, s);
        float q = valid ? s : NEG_INF;
        q += __shfl_xor_sync(0xffffffffu, q, 1);
        q += __shfl_xor_sync(0xffffffffu, q, 2);
        q += __shfl_xor_sync(0xffffffffu, q, 4);
        pe = __expf(q);                      // 0 for invalid (exp(-inf))
        d += pe;
        acc[0] = fmaf(pe, v0.x, acc[0]); acc[1] = fmaf(pe, v0.y, acc[1]);
        acc[2] = fmaf(pe, v0.z, acc[2]); acc[3] = fmaf(pe, v0.w, acc[3]);
        acc[4] = fmaf(pe, v1.x, acc[4]); acc[5] = fmaf(pe, v1.y, acc[5]);
        acc[6] = fmaf(pe, v1.z, acc[6]); acc[7] = fmaf(pe, v1.w, acc[7]);
    }

    // merge quarters (pairwise tree: self-loop quarter-seeds sum exactly to 1x)
    d += __shfl_xor_sync(0xffffffffu, d, 8);
    d += __shfl_xor_sync(0xffffffffu, d, 16);
#pragma unroll
    for (int k = 0; k < 8; k++) acc[k] += __shfl_xor_sync(0xffffffffu, acc[k], 8);
#pragma unroll
    for (int k = 0; k < 8; k++) acc[k] += __shfl_xor_sync(0xffffffffu, acc[k], 16);

    float inv = 1.0f / (d + 1e-16f);
    float4 b0 = *(const float4*)(bias + c0);
    float4 b1 = *(const float4*)(bias + c1);
    float h[8];
    h[0] = acc[0] * inv + b0.x; h[1] = acc[1] * inv + b0.y;
    h[2] = acc[2] * inv + b0.z; h[3] = acc[3] * inv + b0.w;
    h[4] = acc[4] * inv + b1.x; h[5] = acc[5] * inv + b1.y;
    h[6] = acc[6] * inv + b1.z; h[7] = acc[7] * inv + b1.w;
#pragma unroll
    for (int k = 0; k < 8; k++) h[k] = (h[k] > 0.0f) ? h[k] : expm1f(h[k]);

    if (quarter == 0) {
        *(float4*)&sh[warp][c0] = make_float4(h[0], h[1], h[2], h[3]);
        *(float4*)&sh[warp][c1] = make_float4(h[4], h[5], h[6], h[7]);
    }
    __syncwarp();

    // fused 64x64 output GEMM: lane owns out channels c, c+1
    int c = lane << 1;
    ull acc2 = 0ull;
    const float* hr = sh[warp];
#pragma unroll 4
    for (int k4 = 0; k4 < 16; k4++) {
        float4 hq = *(const float4*)&hr[k4 * 4];
        ffma2(acc2, pack2(hq.x, hq.x), *(const ull*)&sW[(k4 * 4 + 0) * OC + c]);
        ffma2(acc2, pack2(hq.y, hq.y), *(const ull*)&sW[(k4 * 4 + 1) * OC + c]);
        ffma2(acc2, pack2(hq.z, hq.z), *(const ull*)&sW[(k4 * 4 + 2) * OC + c]);
        ffma2(acc2, pack2(hq.w, hq.w), *(const ull*)&sW[(k4 * 4 + 3) * OC + c]);
    }
    float o0, o1; unpack2(acc2, o0, o1);
    float2 bl = *(const float2*)(blin + c);
    *(float2*)(out + ((size_t)i << 6) + c) = make_float2(o0 + bl.x, o1 + bl.y);
}

// ---------------- launch ----------------
extern "C" void kernel_launch(void* const* d_in, const int* in_sizes, int n_in,
                              void* d_out, int out_size) {
    const float* x     = (const float*)d_in[0];
    const void*  ei    = d_in[1];
    const float* Wl    = (const float*)d_in[3];
    const float* Wr    = (const float*)d_in[4];
    const float* att   = (const float*)d_in[5];
    const float* bconv = (const float*)d_in[6];
    const float* Wlin  = (const float*)d_in[7];
    const float* blin  = (const float*)d_in[8];
    float* out = (float*)d_out;

    k_pre<<<196, 256>>>(Wl, Wr, Wlin, (const int*)ei);
    k_gh<<<GB + HB, 128>>>(x, ei);
    k_ss<<<SB + SCTB, 256>>>();
    k_aggr<<<(NN + 15) / 16, 512>>>(att, bconv, blin, out);
}

// round 12
// speedup vs baseline: 1.1426x; 1.1018x over previous
#include <cuda_runtime.h>
#include <cstdint>

#define NN 50000
#define NE 1200000
#define INC 128
#define HC 64
#define OC 64
#define SB 196                     // scan blocks (196*256 = 50176 >= NN)
#define GB 1563                    // gemm blocks ((NN+31)/32)
#define HB ((NE + 127) / 128)      // hist blocks at 128 threads
#define SCTB ((NE + 1023) / 1024)  // scatter blocks (4 edges/thread, 256 thr)

#define NEG_INF __int_as_float(0xff800000)

typedef unsigned long long ull;

// ---------------- scratch ----------------
__device__ __align__(16) float g_xl[(size_t)NN * HC];
__device__ __align__(16) float g_xr[(size_t)NN * HC];
__device__ __align__(16) float g_Wt[INC * 128];
__device__ __align__(16) float g_Wlt[HC * OC];
__device__ int   g_cnt[SB * 256];      // degree counts; zeroed by scan for next replay
__device__ int   g_off[NN + 1];
__device__ int   g_srcs[NE];
__device__ __align__(16) ull g_dr[NE]; // packed (dst<<16|src)<<32 | rank
__device__ int   g_flag[SB];           // lookback: 0=invalid 1=agg 2=inclusive
__device__ int   g_agg[SB];
__device__ int   g_incl[SB];
__device__ int   g_scan_done;
__device__ int   g_work;               // work-stealing node counter
__device__ int   g_probe;              // 1 => int32 storage, 0 => int64

// ---------------- helpers ----------------
__device__ __forceinline__ ull pack2(float lo, float hi) {
    ull r; asm("mov.b64 %0, {%1, %2};" : "=l"(r) : "f"(lo), "f"(hi)); return r;
}
__device__ __forceinline__ void unpack2(ull v, float& lo, float& hi) {
    asm("mov.b64 {%0, %1}, %2;" : "=f"(lo), "=f"(hi) : "l"(v));
}
__device__ __forceinline__ void ffma2(ull& d, ull a, ull b) {
    asm("fma.rn.f32x2 %0, %1, %2, %0;" : "+l"(d) : "l"(a), "l"(b));
}
__device__ __forceinline__ ull add2(ull a, ull b) {
    ull r; asm("add.rn.f32x2 %0, %1, %2;" : "=l"(r) : "l"(a), "l"(b)); return r;
}
__device__ __forceinline__ int load_idx(const void* ei, int pos, int is64) {
    int v = is64 ? (int)((const long long*)ei)[pos] : ((const int*)ei)[pos];
    return (v < 0) ? 0 : (v >= NN ? NN - 1 : v);
}

// ---------------- K0: weight transpose + dtype probe + control resets ----------------
__global__ void k_pre(const float* __restrict__ Wl, const float* __restrict__ Wr,
                      const float* __restrict__ Wlin, const int* __restrict__ ei32) {
    int t0 = blockIdx.x * blockDim.x + threadIdx.x;
    if (t0 < 32) {
        int v = 0;
#pragma unroll 8
        for (int it = 0; it < 32; it++) v |= ei32[2 * (t0 + 32 * it) + 1];
#pragma unroll
        for (int o = 16; o; o >>= 1) v |= __shfl_xor_sync(0xffffffffu, v, o);
        if (t0 == 0) { g_probe = (v != 0) ? 1 : 0; g_scan_done = 0; g_work = 0; }
    }
    if (t0 < SB) g_flag[t0] = 0;
    if (t0 < INC * 128) {
        int k = t0 >> 7, ch = t0 & 127;
        g_Wt[t0] = (ch < HC) ? Wl[ch * INC + k] : Wr[(ch - HC) * INC + k];
    }
    if (t0 < HC * OC) {
        int k = t0 >> 6, o = t0 & 63;
        g_Wlt[t0] = Wlin[o * HC + k];
    }
}

// ---------------- K1: MERGED projection GEMM + histogram/pack ----------------
__global__ void __launch_bounds__(128) k_gh(const float* __restrict__ x,
                                            const void* __restrict__ ei) {
    __shared__ __align__(16) float xs2[32 * INC];
    int tid = threadIdx.x;

    if (blockIdx.x >= GB) {
        int is64 = (g_probe == 0);
        int e = (blockIdx.x - GB) * 128 + tid;
        if (e < NE) {
            int d = load_idx(ei, NE + e, is64);
            int s = load_idx(ei, e, is64);
            int r = atomicAdd(&g_cnt[d], 1);
            g_dr[e] = ((ull)(((unsigned)d << 16) | (unsigned)s) << 32) | (unsigned)r;
        }
        return;
    }

    int row0 = blockIdx.x * 32;
    int nrows = NN - row0; if (nrows > 32) nrows = 32;

    for (int i = tid; i < 32 * (INC / 4); i += 128) {
        int r = i >> 5;
        int k4 = (i & 31) << 2;
        if (r < nrows) {
            float4 v = *(const float4*)(x + (size_t)(row0 + r) * INC + k4);
            float* b = xs2 + (r >> 1) * (2 * INC) + (r & 1);
            b[2 * k4 + 0] = v.x; b[2 * k4 + 2] = v.y;
            b[2 * k4 + 4] = v.z; b[2 * k4 + 6] = v.w;
        }
    }
    __syncthreads();

    int warp = tid >> 5, lane = tid & 31;
    int c = lane << 2;
    ull acc[4][4];
#pragma unroll
    for (int q = 0; q < 4; q++)
#pragma unroll
        for (int j = 0; j < 4; j++) acc[q][j] = 0ull;

    const float* xb = xs2 + (warp * 4) * (2 * INC);
#pragma unroll 8
    for (int k = 0; k < INC; k++) {
        float4 w = *(const float4*)(g_Wt + (k << 7) + c);
        ull w0 = pack2(w.x, w.x), w1 = pack2(w.y, w.y);
        ull w2 = pack2(w.z, w.z), w3 = pack2(w.w, w.w);
#pragma unroll
        for (int q = 0; q < 4; q++) {
            ull xp = *(const ull*)(xb + q * (2 * INC) + 2 * k);
            ffma2(acc[q][0], xp, w0);
            ffma2(acc[q][1], xp, w1);
            ffma2(acc[q][2], xp, w2);
            ffma2(acc[q][3], xp, w3);
        }
    }

    float* base = (c < HC) ? (g_xl + c) : (g_xr + (c - HC));
#pragma unroll
    for (int q = 0; q < 4; q++) {
        int re = row0 + warp * 8 + q * 2;
        if (re >= NN) break;
        float lo0, hi0, lo1, hi1, lo2, hi2, lo3, hi3;
        unpack2(acc[q][0], lo0, hi0); unpack2(acc[q][1], lo1, hi1);
        unpack2(acc[q][2], lo2, hi2); unpack2(acc[q][3], lo3, hi3);
        *(float4*)(base + (size_t)re * HC) = make_float4(lo0, lo1, lo2, lo3);
        if (re + 1 < NN)
            *(float4*)(base + (size_t)(re + 1) * HC) = make_float4(hi0, hi1, hi2, hi3);
    }
}

// ---------------- K2: MERGED decoupled-lookback scan + scatter ----------------
__global__ void __launch_bounds__(256) k_ss() {
    int tid = threadIdx.x;
    int b = blockIdx.x;

    if (b < SB) {
        __shared__ int wsum[8];
        __shared__ int s_base;
        int i = b * 256 + tid;
        int v = g_cnt[i];
        g_cnt[i] = 0;
        int lane = tid & 31, wid = tid >> 5;
        int xv = v;
#pragma unroll
        for (int o = 1; o < 32; o <<= 1) {
            int y = __shfl_up_sync(0xffffffffu, xv, o);
            if (lane >= o) xv += y;
        }
        if (lane == 31) wsum[wid] = xv;
        __syncthreads();
        if (tid < 8) {
            int w = wsum[tid];
#pragma unroll
            for (int o = 1; o < 8; o <<= 1) {
                int y = __shfl_up_sync(0x000000ffu, w, o);
                if (tid >= o) w += y;
            }
            wsum[tid] = w;
        }
        __syncthreads();
        int excl = xv - v + ((wid > 0) ? wsum[wid - 1] : 0);
        int T = wsum[7];

        if (b == 0) {
            if (tid == 0) {
                g_incl[0] = T;
                __threadfence();
                atomicExch(&g_flag[0], 2);
                s_base = 0;
            }
        } else if (tid < 32) {
            if (tid == 0) {
                g_agg[b] = T;
                __threadfence();
                atomicExch(&g_flag[b], 1);
            }
            __syncwarp();
            int sum = 0;
            int p = b - 1;
            for (;;) {
                int idx = p - tid;
                int f = 0;
                if (idx >= 0) {
                    do { f = atomicAdd(&g_flag[idx], 0); } while (f == 0);
                }
                unsigned m2 = __ballot_sync(0xffffffffu, (idx >= 0) && (f == 2));
                int kcut = m2 ? (__ffs(m2) - 1) : 32;
                __threadfence();
                int contrib = 0;
                if (idx >= 0 && tid <= kcut)
                    contrib = (tid == kcut) ? atomicAdd(&g_incl[idx], 0)
                                            : atomicAdd(&g_agg[idx], 0);
#pragma unroll
                for (int o = 16; o; o >>= 1) contrib += __shfl_xor_sync(0xffffffffu, contrib, o);
                sum += contrib;
                if (m2) break;
                p -= 32;
            }
            if (tid == 0) {
                g_incl[b] = sum + T;
                __threadfence();
                atomicExch(&g_flag[b], 2);
                s_base = sum;
            }
        }
        __syncthreads();
        if (i < NN) g_off[i] = excl + s_base;
        if (b == 0 && tid == 0) g_off[NN] = NE;
        __threadfence();
        __syncthreads();
        if (tid == 0) atomicAdd(&g_scan_done, 1);
        return;
    }

    if (tid == 0) {
        while (atomicAdd(&g_scan_done, 0) < SB) __nanosleep(64);
    }
    __syncthreads();
    __threadfence();

    int e0 = (b - SB) * 1024 + tid;
#pragma unroll
    for (int k = 0; k < 4; k++) {
        int e = e0 + k * 256;
        if (e < NE) {
            ull dr = g_dr[e];
            unsigned hi = (unsigned)(dr >> 32);
            int d = hi >> 16;
            int s = hi & 0xFFFF;
            int r = (int)(unsigned)dr;
            g_srcs[g_off[d] + r] = s;
        }
    }
}

// ---------------- K3: persistent work-stealing aggregation, f32x2 edge math ----------------
// Warp grabs node IDs from g_work (no block tails, no wave quantization).
// Logit split: s = dot(a6,v) + K + dot(a4,|v+xr|), K = dot(a6,xr) hoisted per node.
// a6-part and u=v+xr run packed f32x2; |u| part scalar FFMA (abs = free modifier).
// Self-loop seed scaled 0.25 (runs in all 4 quarters; merge tree sums exactly to 1x).
__global__ void __launch_bounds__(512, 2) k_aggr(const float* __restrict__ att,
                                                 const float* __restrict__ bias,
                                                 const float* __restrict__ blin,
                                                 float* __restrict__ out) {
    __shared__ __align__(16) float sW[HC * OC];   // 16 KB
    __shared__ __align__(16) float sh[16][HC];    // 4 KB
    int tid = threadIdx.x;
    for (int idx = tid; idx < HC * OC / 4; idx += 512)
        *(float4*)&sW[idx * 4] = *(const float4*)&g_Wlt[idx * 4];
    __syncthreads();

    int warp = tid >> 5, lane = tid & 31;
    int quarter = lane >> 3, l8 = lane & 7;
    int c0 = l8 * 4, c1 = 32 + l8 * 4;

    // packed 0.6*att pairs, scalar 0.4*att
    float4 at0 = *(const float4*)(att + c0);
    float4 at1 = *(const float4*)(att + c1);
    ull a6p00 = pack2(0.6f * at0.x, 0.6f * at0.y);
    ull a6p01 = pack2(0.6f * at0.z, 0.6f * at0.w);
    ull a6p10 = pack2(0.6f * at1.x, 0.6f * at1.y);
    ull a6p11 = pack2(0.6f * at1.z, 0.6f * at1.w);
    float a40x = 0.4f * at0.x, a40y = 0.4f * at0.y, a40z = 0.4f * at0.z, a40w = 0.4f * at0.w;
    float a41x = 0.4f * at1.x, a41y = 0.4f * at1.y, a41z = 0.4f * at1.z, a41w = 0.4f * at1.w;

    for (;;) {
        int n;
        if (lane == 0) n = atomicAdd(&g_work, 1);
        n = __shfl_sync(0xffffffffu, n, 0);
        if (n >= NN) break;

        const float* xri = g_xr + ((unsigned)n << 6);
        ulonglong2 xrp0 = *(const ulonglong2*)(xri + c0);
        ulonglong2 xrp1 = *(const ulonglong2*)(xri + c1);

        // K = dot(a6, xr) for this lane's 8 channels
        ull kp = 0ull;
        ffma2(kp, xrp0.x, a6p00); ffma2(kp, xrp0.y, a6p01);
        ffma2(kp, xrp1.x, a6p10); ffma2(kp, xrp1.y, a6p11);
        float klo, khi; unpack2(kp, klo, khi);
        float K = klo + khi;

        ull accp[4] = {0ull, 0ull, 0ull, 0ull};
        float d;

        // ---- self loop (all quarters, 0.25 scale) ----
        const float* xli = g_xl + ((unsigned)n << 6);
        ulonglong2 v0p = *(const ulonglong2*)(xli + c0);
        ulonglong2 v1p = *(const ulonglong2*)(xli + c1);
        {
            ull sp = 0ull;
            ffma2(sp, v0p.x, a6p00); ffma2(sp, v0p.y, a6p01);
            ffma2(sp, v1p.x, a6p10); ffma2(sp, v1p.y, a6p11);
            ull u0 = add2(v0p.x, xrp0.x), u1 = add2(v0p.y, xrp0.y);
            ull u2 = add2(v1p.x, xrp1.x), u3 = add2(v1p.y, xrp1.y);
            float ul, uh, sa = K;
            unpack2(u0, ul, uh); sa = fmaf(fabsf(ul), a40x, sa); sa = fmaf(fabsf(uh), a40y, sa);
            unpack2(u1, ul, uh); sa = fmaf(fabsf(ul), a40z, sa); sa = fmaf(fabsf(uh), a40w, sa);
            unpack2(u2, ul, uh); sa = fmaf(fabsf(ul), a41x, sa); sa = fmaf(fabsf(uh), a41y, sa);
            unpack2(u3, ul, uh); sa = fmaf(fabsf(ul), a41z, sa); sa = fmaf(fabsf(uh), a41w, sa);
            float slo, shi; unpack2(sp, slo, shi);
            float s = sa + slo + shi;
            s += __shfl_xor_sync(0xffffffffu, s, 1);
            s += __shfl_xor_sync(0xffffffffu, s, 2);
            s += __shfl_xor_sync(0xffffffffu, s, 4);
            float pe = 0.25f * __expf(s);
            d = pe;
            ull pep = pack2(pe, pe);
            ffma2(accp[0], pep, v0p.x); ffma2(accp[1], pep, v0p.y);
            ffma2(accp[2], pep, v1p.x); ffma2(accp[3], pep, v1p.y);
        }

        // ---- edges: 4 in flight (one per quarter), src prefetch ----
        int off = g_off[n], end = g_off[n + 1];
        int my = off + quarter;
        bool vcur = (my < end);
        int jcur = vcur ? g_srcs[my] : n;
        for (int e = off; e < end; e += 4) {
            int myn = my + 4;
            bool vn = (myn < end);
            int jn = vn ? g_srcs[myn] : n;      // prefetch next src index

            const float* vp = g_xl + ((unsigned)jcur << 6);
            v0p = *(const ulonglong2*)(vp + c0);
            v1p = *(const ulonglong2*)(vp + c1);
            ull sp = 0ull;
            ffma2(sp, v0p.x, a6p00); ffma2(sp, v0p.y, a6p01);
            ffma2(sp, v1p.x, a6p10); ffma2(sp, v1p.y, a6p11);
            ull u0 = add2(v0p.x, xrp0.x), u1 = add2(v0p.y, xrp0.y);
            ull u2 = add2(v1p.x, xrp1.x), u3 = add2(v1p.y, xrp1.y);
            float ul, uh, sa = K;
            unpack2(u0, ul, uh); sa = fmaf(fabsf(ul), a40x, sa); sa = fmaf(fabsf(uh), a40y, sa);
            unpack2(u1, ul, uh); sa = fmaf(fabsf(ul), a40z, sa); sa = fmaf(fabsf(uh), a40w, sa);
            unpack2(u2, ul, uh); sa = fmaf(fabsf(ul), a41x, sa); sa = fmaf(fabsf(uh), a41y, sa);
            unpack2(u3, ul, uh); sa = fmaf(fabsf(ul), a41z, sa); sa = fmaf(fabsf(uh), a41w, sa);
            float slo, shi; unpack2(sp, slo, shi);
            float s = sa + slo + shi;
            float q = vcur ? s : NEG_INF;
            q += __shfl_xor_sync(0xffffffffu, q, 1);
            q += __shfl_xor_sync(0xffffffffu, q, 2);
            q += __shfl_xor_sync(0xffffffffu, q, 4);
            float pe = __expf(q);               // 0 for invalid
            d += pe;
            ull pep = pack2(pe, pe);
            ffma2(accp[0], pep, v0p.x); ffma2(accp[1], pep, v0p.y);
            ffma2(accp[2], pep, v1p.x); ffma2(accp[3], pep, v1p.y);

            my = myn; vcur = vn; jcur = jn;
        }

        // unpack + merge quarters
        float acc[8];
        unpack2(accp[0], acc[0], acc[1]); unpack2(accp[1], acc[2], acc[3]);
        unpack2(accp[2], acc[4], acc[5]); unpack2(accp[3], acc[6], acc[7]);
        d += __shfl_xor_sync(0xffffffffu, d, 8);
        d += __shfl_xor_sync(0xffffffffu, d, 16);
#pragma unroll
        for (int k = 0; k < 8; k++) acc[k] += __shfl_xor_sync(0xffffffffu, acc[k], 8);
#pragma unroll
        for (int k = 0; k < 8; k++) acc[k] += __shfl_xor_sync(0xffffffffu, acc[k], 16);

        float inv = 1.0f / (d + 1e-16f);
        float4 b0 = *(const float4*)(bias + c0);
        float4 b1 = *(const float4*)(bias + c1);
        float h[8];
        h[0] = acc[0] * inv + b0.x; h[1] = acc[1] * inv + b0.y;
        h[2] = acc[2] * inv + b0.z; h[3] = acc[3] * inv + b0.w;
        h[4] = acc[4] * inv + b1.x; h[5] = acc[5] * inv + b1.y;
        h[6] = acc[6] * inv + b1.z; h[7] = acc[7] * inv + b1.w;
#pragma unroll
        for (int k = 0; k < 8; k++) h[k] = (h[k] > 0.0f) ? h[k] : expm1f(h[k]);

        if (quarter == 0) {
            *(float4*)&sh[warp][c0] = make_float4(h[0], h[1], h[2], h[3]);
            *(float4*)&sh[warp][c1] = make_float4(h[4], h[5], h[6], h[7]);
        }
        __syncwarp();

        // fused 64x64 output GEMM: lane owns out channels c, c+1
        int c = lane << 1;
        ull acc2 = 0ull;
        const float* hr = sh[warp];
#pragma unroll 4
        for (int k4 = 0; k4 < 16; k4++) {
            float4 hq = *(const float4*)&hr[k4 * 4];
            ffma2(acc2, pack2(hq.x, hq.x), *(const ull*)&sW[(k4 * 4 + 0) * OC + c]);
            ffma2(acc2, pack2(hq.y, hq.y), *(const ull*)&sW[(k4 * 4 + 1) * OC + c]);
            ffma2(acc2, pack2(hq.z, hq.z), *(const ull*)&sW[(k4 * 4 + 2) * OC + c]);
            ffma2(acc2, pack2(hq.w, hq.w), *(const ull*)&sW[(k4 * 4 + 3) * OC + c]);
        }
        float o0, o1; unpack2(acc2, o0, o1);
        float2 bl = *(const float2*)(blin + c);
        *(float2*)(out + ((size_t)n << 6) + c) = make_float2(o0 + bl.x, o1 + bl.y);
        __syncwarp();                           // sh reuse guard for next node
    }
}

// ---------------- launch ----------------
extern "C" void kernel_launch(void* const* d_in, const int* in_sizes, int n_in,
                              void* d_out, int out_size) {
    const float* x     = (const float*)d_in[0];
    const void*  ei    = d_in[1];
    const float* Wl    = (const float*)d_in[3];
    const float* Wr    = (const float*)d_in[4];
    const float* att   = (const float*)d_in[5];
    const float* bconv = (const float*)d_in[6];
    const float* Wlin  = (const float*)d_in[7];
    const float* blin  = (const float*)d_in[8];
    float* out = (float*)d_out;

    k_pre<<<196, 256>>>(Wl, Wr, Wlin, (const int*)ei);
    k_gh<<<GB + HB, 128>>>(x, ei);
    k_ss<<<SB + SCTB, 256>>>();
    k_aggr<<<296, 512>>>(att, bconv, blin, out);
}